// round 3
// baseline (speedup 1.0000x reference)
#include <cuda_runtime.h>

// Problem constants
// X:(2,2048,16,64) A:(2,2048,16) B,C:(2,2048,16,64)
// r,k,v,w,bonus:(32,2048,64)  out:(2,2048,1024) f32
#define THREADS 128
#define SSTRIDE 68                      // padded shared row stride (floats), 16B-aligned, low-conflict
#define SMEM_FLOATS (6 * 64 * SSTRIDE + 256)
#define SMEM_BYTES  (SMEM_FLOATS * 4)   // 105,472 B

// ---------------------------------------------------------------------------
// cp.async helpers
// ---------------------------------------------------------------------------
__device__ __forceinline__ void cp_async16(float* dst, const float* src) {
    unsigned s = (unsigned)__cvta_generic_to_shared(dst);
    asm volatile("cp.async.ca.shared.global [%0], [%1], 16;\n" :: "r"(s), "l"(src));
}
__device__ __forceinline__ void cp_commit() { asm volatile("cp.async.commit_group;\n"); }
__device__ __forceinline__ void cp_wait1()  { asm volatile("cp.async.wait_group 1;\n" ::: "memory"); }

// 4x8 outer-product FMA block
#define FMA32(ACC, a4, b0, b1) do{ \
  ACC[0][0] += a4.x*b0.x; ACC[0][1] += a4.x*b0.y; ACC[0][2] += a4.x*b0.z; ACC[0][3] += a4.x*b0.w; \
  ACC[0][4] += a4.x*b1.x; ACC[0][5] += a4.x*b1.y; ACC[0][6] += a4.x*b1.z; ACC[0][7] += a4.x*b1.w; \
  ACC[1][0] += a4.y*b0.x; ACC[1][1] += a4.y*b0.y; ACC[1][2] += a4.y*b0.z; ACC[1][3] += a4.y*b0.w; \
  ACC[1][4] += a4.y*b1.x; ACC[1][5] += a4.y*b1.y; ACC[1][6] += a4.y*b1.z; ACC[1][7] += a4.y*b1.w; \
  ACC[2][0] += a4.z*b0.x; ACC[2][1] += a4.z*b0.y; ACC[2][2] += a4.z*b0.z; ACC[2][3] += a4.z*b0.w; \
  ACC[2][4] += a4.z*b1.x; ACC[2][5] += a4.z*b1.y; ACC[2][6] += a4.z*b1.z; ACC[2][7] += a4.z*b1.w; \
  ACC[3][0] += a4.w*b0.x; ACC[3][1] += a4.w*b0.y; ACC[3][2] += a4.w*b0.z; ACC[3][3] += a4.w*b0.w; \
  ACC[3][4] += a4.w*b1.x; ACC[3][5] += a4.w*b1.y; ACC[3][6] += a4.w*b1.z; ACC[3][7] += a4.w*b1.w; \
}while(0)

// ---------------------------------------------------------------------------
// WKV-7 recurrence: one CTA per batch-head (bh = blockIdx.x, 0..31)
// Thread t: row i = t&63, half = t>>6 owns 32 state columns in registers.
// Inputs staged 16 timesteps at a time through double-buffered cp.async.
// ---------------------------------------------------------------------------
__device__ void wkv_block(float* smem, const float* R, const float* K, const float* V,
                          const float* W, const float* BN, float* out)
{
    const int bh   = blockIdx.x;
    const int b    = bh >> 4, h = bh & 15;
    const int tid  = threadIdx.x;
    const int i    = tid & 63;
    const int off  = (tid >> 6) * 32;
    const int base = bh * (2048 * 64);

    float* buf      = smem;           // 2 stages * 5 arrays * 1024 floats = 10240
    float* sh_part  = smem + 10240;   // 128
    float* sh_delta = sh_part + 128;  // 64

    float S[32];
    #pragma unroll
    for (int q = 0; q < 32; ++q) S[q] = 0.f;

    const float* g0 = R + base;
    const float* g1 = K + base;
    const float* g2 = V + base;
    const float* g3 = W + base;
    const float* g4 = BN + base;

    // prologue: issue blocks 0 and 1
    #pragma unroll
    for (int pb = 0; pb < 2; ++pb) {
        float* d = buf + pb * 5120;
        const float* srcs[5] = { g0 + pb*1024, g1 + pb*1024, g2 + pb*1024, g3 + pb*1024, g4 + pb*1024 };
        #pragma unroll
        for (int a = 0; a < 5; ++a) {
            float* da = d + a * 1024;
            const float* sa = srcs[a];
            for (int q = tid; q < 256; q += THREADS) cp_async16(da + q*4, sa + q*4);
        }
        cp_commit();
    }

    for (int blk = 0; blk < 128; ++blk) {
        cp_wait1();
        __syncthreads();
        const int stage = blk & 1;
        const float* bb = buf + stage * 5120;
        const float* Rb = bb;
        const float* Kb = bb + 1024;
        const float* Vb = bb + 2048;
        const float* Wb = bb + 3072;
        const float* Bb = bb + 4096;
        const int t0 = blk * 16;

        for (int s = 0; s < 16; ++s) {
            const float* Kr = Kb + s * 64;
            float kf[32];
            float a0 = 0.f, a1 = 0.f, a2 = 0.f, a3 = 0.f;
            #pragma unroll
            for (int q = 0; q < 8; ++q) {
                float4 k4 = *(const float4*)(Kr + off + q*4);
                kf[q*4+0] = k4.x; kf[q*4+1] = k4.y; kf[q*4+2] = k4.z; kf[q*4+3] = k4.w;
                a0 += S[q*4+0]*k4.x; a1 += S[q*4+1]*k4.y;
                a2 += S[q*4+2]*k4.z; a3 += S[q*4+3]*k4.w;
            }
            sh_part[tid] = (a0 + a1) + (a2 + a3);
            __syncthreads();
            if (tid < 64) {
                float Sk = sh_part[i] + sh_part[i + 64];
                sh_delta[i] = Vb[s*64 + i] - Sk;
            }
            __syncthreads();
            float wi  = Wb[s*64 + i];
            float bki = Bb[s*64 + i] * Kr[i];
            float y0 = 0.f, y1 = 0.f, y2 = 0.f, y3 = 0.f;
            #pragma unroll
            for (int q = 0; q < 8; ++q) {
                float4 d4 = *(const float4*)(sh_delta + off + q*4);
                S[q*4+0] = S[q*4+0]*wi + bki*d4.x; y0 += S[q*4+0]*kf[q*4+0];
                S[q*4+1] = S[q*4+1]*wi + bki*d4.y; y1 += S[q*4+1]*kf[q*4+1];
                S[q*4+2] = S[q*4+2]*wi + bki*d4.z; y2 += S[q*4+2]*kf[q*4+2];
                S[q*4+3] = S[q*4+3]*wi + bki*d4.w; y3 += S[q*4+3]*kf[q*4+3];
            }
            sh_part[tid] = (y0 + y1) + (y2 + y3);
            __syncthreads();
            if (tid < 64) {
                float y = Rb[s*64 + i] * (sh_part[i] + sh_part[i + 64]);
                atomicAdd(out + (b*2048 + t0 + s)*1024 + h*64 + i, y);
            }
            __syncthreads();
        }

        // refill this stage for block blk+2
        const int nb = blk + 2;
        if (nb < 128) {
            float* d = buf + stage * 5120;
            const float* srcs[5] = { g0 + nb*1024, g1 + nb*1024, g2 + nb*1024, g3 + nb*1024, g4 + nb*1024 };
            #pragma unroll
            for (int a = 0; a < 5; ++a) {
                float* da = d + a * 1024;
                const float* sa = srcs[a];
                for (int q = tid; q < 256; q += THREADS) cp_async16(da + q*4, sa + q*4);
            }
        }
        cp_commit();
    }
}

// ---------------------------------------------------------------------------
// Mamba2 SSD chunked scan: one CTA per (b,h) (blockIdx.x - 32), sequential
// over 32 chunks of 64 tokens. State S[p][n] lives in registers (GEMM4
// accumulator tiles); a shared transposed copy St[n][p] feeds GEMM3.
// ---------------------------------------------------------------------------
__device__ void ssd_block(float* smem, const float* Xg, const float* Ag,
                          const float* Bg, const float* Cg, float* out)
{
    const int sb  = blockIdx.x - 32;
    const int b   = sb >> 4, h = sb & 15;
    const int tid = threadIdx.x;
    const int r0  = (tid & 15) * 4;   // a-dim tile base (l or p)
    const int c0  = (tid >> 4) * 8;   // b-dim tile base (s, p, or n)

    float* Ct   = smem;                  // [n][l], pre-scaled by exp(cum[l])
    float* Bt   = Ct  + 64 * SSTRIDE;    // [n][s], raw B
    float* Brw  = Bt  + 64 * SSTRIDE;    // [l][n], B * exp(Atot - cum[l])
    float* sX   = Brw + 64 * SSTRIDE;    // [l][p]
    float* Gt   = sX  + 64 * SSTRIDE;    // [s][l]
    float* St   = Gt  + 64 * SSTRIDE;    // [n][p], incoming state
    float* cum  = St  + 64 * SSTRIDE;    // [64]
    float* ecl  = cum + 64;              // exp(cum)
    float* recl = ecl + 64;              // exp(-cum)
    float* misc = recl + 64;             // [0] = exp(Atot)

    for (int idx = tid; idx < 64 * SSTRIDE; idx += THREADS) St[idx] = 0.f;

    float Sreg[4][8];
    #pragma unroll
    for (int q = 0; q < 4; ++q)
        #pragma unroll
        for (int j = 0; j < 8; ++j) Sreg[q][j] = 0.f;
    __syncthreads();

    for (int c = 0; c < 32; ++c) {
        const int tb = c * 64;

        // A row -> inclusive cumsum -> exp tables
        if (tid < 64) cum[tid] = Ag[(b*2048 + tb + tid)*16 + h];
        __syncthreads();
        if (tid == 0) {
            float s = 0.f;
            #pragma unroll
            for (int l = 0; l < 64; ++l) { s += cum[l]; cum[l] = s; }
        }
        __syncthreads();
        if (tid < 64) { float cl = cum[tid]; ecl[tid] = __expf(cl); recl[tid] = __expf(-cl); }
        if (tid == 0) misc[0] = __expf(cum[63]);
        __syncthreads();
        const float eA = misc[0];

        // load B, C, X tiles (with on-the-fly transposes + decay scaling)
        for (int idx = tid; idx < 4096; idx += THREADS) {
            int row = idx >> 6, col = idx & 63;
            int gix = ((b*2048 + tb + row)*16 + h)*64 + col;
            float bv = Bg[gix];
            Bt [col*SSTRIDE + row] = bv;
            Brw[row*SSTRIDE + col] = bv * (eA * recl[row]);
            Ct [col*SSTRIDE + row] = Cg[gix] * ecl[row];
            sX [row*SSTRIDE + col] = Xg[gix];
        }
        __syncthreads();

        // GEMM1: G[l,s] = sum_n Ctw[n][l] * B[n][s]   (Ctw includes exp(cum[l]))
        float acc[4][8];
        #pragma unroll
        for (int q = 0; q < 4; ++q)
            #pragma unroll
            for (int j = 0; j < 8; ++j) acc[q][j] = 0.f;
        #pragma unroll 4
        for (int n = 0; n < 64; ++n) {
            float4 a4 = *(const float4*)(Ct + n*SSTRIDE + r0);
            float4 b0 = *(const float4*)(Bt + n*SSTRIDE + c0);
            float4 b1 = *(const float4*)(Bt + n*SSTRIDE + c0 + 4);
            FMA32(acc, a4, b0, b1);
        }
        // epilogue: mask s<=l, scale by exp(-cum[s]); store transposed Gt[s][l]
        #pragma unroll
        for (int ss = 0; ss < 8; ++ss) {
            int sidx = c0 + ss;
            float rs = recl[sidx];
            float4 v;
            v.x = (sidx <= r0 + 0) ? acc[0][ss] * rs : 0.f;
            v.y = (sidx <= r0 + 1) ? acc[1][ss] * rs : 0.f;
            v.z = (sidx <= r0 + 2) ? acc[2][ss] * rs : 0.f;
            v.w = (sidx <= r0 + 3) ? acc[3][ss] * rs : 0.f;
            *(float4*)(Gt + sidx*SSTRIDE + r0) = v;
        }
        __syncthreads();

        // GEMM2+3 fused: Y[l,p] = sum_s G[l,s]X[s,p] + sum_n Ctw[n][l]St[n][p]
        #pragma unroll
        for (int q = 0; q < 4; ++q)
            #pragma unroll
            for (int j = 0; j < 8; ++j) acc[q][j] = 0.f;
        #pragma unroll 4
        for (int s = 0; s < 64; ++s) {
            float4 a4 = *(const float4*)(Gt + s*SSTRIDE + r0);
            float4 b0 = *(const float4*)(sX + s*SSTRIDE + c0);
            float4 b1 = *(const float4*)(sX + s*SSTRIDE + c0 + 4);
            FMA32(acc, a4, b0, b1);
        }
        #pragma unroll 4
        for (int n = 0; n < 64; ++n) {
            float4 a4 = *(const float4*)(Ct + n*SSTRIDE + r0);
            float4 b0 = *(const float4*)(St + n*SSTRIDE + c0);
            float4 b1 = *(const float4*)(St + n*SSTRIDE + c0 + 4);
            FMA32(acc, a4, b0, b1);
        }
        #pragma unroll
        for (int ll = 0; ll < 4; ++ll) {
            int o = (b*2048 + tb + r0 + ll)*1024 + h*64 + c0;
            #pragma unroll
            for (int pp = 0; pp < 8; ++pp) atomicAdd(out + o + pp, acc[ll][pp]);
        }

        // GEMM4 (state update): S[p,n] = eA*S + sum_l X[l,p] * Brw[l,n]
        #pragma unroll
        for (int q = 0; q < 4; ++q)
            #pragma unroll
            for (int j = 0; j < 8; ++j) Sreg[q][j] *= eA;
        #pragma unroll 4
        for (int l = 0; l < 64; ++l) {
            float4 a4 = *(const float4*)(sX  + l*SSTRIDE + r0);
            float4 b0 = *(const float4*)(Brw + l*SSTRIDE + c0);
            float4 b1 = *(const float4*)(Brw + l*SSTRIDE + c0 + 4);
            FMA32(Sreg, a4, b0, b1);
        }
        __syncthreads();   // all GEMM3 reads of St done before overwrite
        #pragma unroll
        for (int j = 0; j < 8; ++j) {
            float4 v = make_float4(Sreg[0][j], Sreg[1][j], Sreg[2][j], Sreg[3][j]);
            *(float4*)(St + (c0 + j)*SSTRIDE + r0) = v;
        }
        __syncthreads();
    }
}

// ---------------------------------------------------------------------------
__global__ void __launch_bounds__(256)
zero_kernel(float4* out)
{
    out[blockIdx.x * 256 + threadIdx.x] = make_float4(0.f, 0.f, 0.f, 0.f);
}

__global__ void __launch_bounds__(THREADS, 1)
fused_kernel(const float* __restrict__ X, const float* __restrict__ A,
             const float* __restrict__ B, const float* __restrict__ C,
             const float* __restrict__ R, const float* __restrict__ K,
             const float* __restrict__ V, const float* __restrict__ W,
             const float* __restrict__ BN, float* __restrict__ out)
{
    extern __shared__ float smem[];
    if (blockIdx.x < 32) wkv_block(smem, R, K, V, W, BN, out);
    else                 ssd_block(smem, X, A, B, C, out);
}

extern "C" void kernel_launch(void* const* d_in, const int* in_sizes, int n_in,
                              void* d_out, int out_size)
{
    const float* X  = (const float*)d_in[0];
    const float* A  = (const float*)d_in[1];
    const float* B  = (const float*)d_in[2];
    const float* C  = (const float*)d_in[3];
    const float* R  = (const float*)d_in[4];
    const float* K  = (const float*)d_in[5];
    const float* V  = (const float*)d_in[6];
    const float* W  = (const float*)d_in[7];
    const float* BN = (const float*)d_in[8];
    float* out = (float*)d_out;

    // out_size = 2*2048*1024 = 4,194,304 floats = 1,048,576 float4
    zero_kernel<<<4096, 256>>>((float4*)out);

    cudaFuncSetAttribute(fused_kernel, cudaFuncAttributeMaxDynamicSharedMemorySize, SMEM_BYTES);
    fused_kernel<<<64, THREADS, SMEM_BYTES>>>(X, A, B, C, R, K, V, W, BN, out);
}

// round 6
// speedup vs baseline: 1.0374x; 1.0374x over previous
#include <cuda_runtime.h>

// Problem constants
// X:(2,2048,16,64) A:(2,2048,16) B,C:(2,2048,16,64)
// r,k,v,w,bonus:(32,2048,64)  out:(2,2048,1024) f32
#define THREADS 128
#define SSTRIDE 68                      // padded shared row stride (floats)
#define SMEM_FLOATS (6 * 64 * SSTRIDE + 256)
#define SMEM_BYTES  (SMEM_FLOATS * 4)   // 105,472 B

typedef unsigned long long u64;

// ---------------------------------------------------------------------------
// packed f32x2 helpers (Blackwell sm_103a; ptxas never auto-fuses these)
// ---------------------------------------------------------------------------
__device__ __forceinline__ void fma2(u64& d, u64 a, u64 b, u64 c) {
    asm("fma.rn.f32x2 %0, %1, %2, %3;" : "=l"(d) : "l"(a), "l"(b), "l"(c));
}
__device__ __forceinline__ void mul2(u64& d, u64 a, u64 b) {
    asm("mul.rn.f32x2 %0, %1, %2;" : "=l"(d) : "l"(a), "l"(b));
}
__device__ __forceinline__ void add2(u64& d, u64 a, u64 b) {
    asm("add.rn.f32x2 %0, %1, %2;" : "=l"(d) : "l"(a), "l"(b));
}
__device__ __forceinline__ u64 pack2(float lo, float hi) {
    u64 r;
    asm("mov.b64 %0, {%1, %2};" : "=l"(r) : "r"(__float_as_uint(lo)), "r"(__float_as_uint(hi)));
    return r;
}
__device__ __forceinline__ float2 unpack2(u64 v) {
    unsigned lo, hi;
    asm("mov.b64 {%0, %1}, %2;" : "=r"(lo), "=r"(hi) : "l"(v));
    return make_float2(__uint_as_float(lo), __uint_as_float(hi));
}

// ---------------------------------------------------------------------------
// cp.async helpers
// ---------------------------------------------------------------------------
__device__ __forceinline__ void cp_async16(float* dst, const float* src) {
    unsigned s = (unsigned)__cvta_generic_to_shared(dst);
    asm volatile("cp.async.ca.shared.global [%0], [%1], 16;\n" :: "r"(s), "l"(src));
}
__device__ __forceinline__ void cp_commit() { asm volatile("cp.async.commit_group;\n"); }
__device__ __forceinline__ void cp_wait1()  { asm volatile("cp.async.wait_group 1;\n" ::: "memory"); }

// packed 4x8 outer-product: a4 scalars broadcast, bA/bB are 4 packed col pairs
#define FMA32P(ACC, a4, bA, bB) do{ u64 _pa; \
  _pa = pack2(a4.x, a4.x); \
  fma2(ACC[0][0],_pa,bA.x,ACC[0][0]); fma2(ACC[0][1],_pa,bA.y,ACC[0][1]); \
  fma2(ACC[0][2],_pa,bB.x,ACC[0][2]); fma2(ACC[0][3],_pa,bB.y,ACC[0][3]); \
  _pa = pack2(a4.y, a4.y); \
  fma2(ACC[1][0],_pa,bA.x,ACC[1][0]); fma2(ACC[1][1],_pa,bA.y,ACC[1][1]); \
  fma2(ACC[1][2],_pa,bB.x,ACC[1][2]); fma2(ACC[1][3],_pa,bB.y,ACC[1][3]); \
  _pa = pack2(a4.z, a4.z); \
  fma2(ACC[2][0],_pa,bA.x,ACC[2][0]); fma2(ACC[2][1],_pa,bA.y,ACC[2][1]); \
  fma2(ACC[2][2],_pa,bB.x,ACC[2][2]); fma2(ACC[2][3],_pa,bB.y,ACC[2][3]); \
  _pa = pack2(a4.w, a4.w); \
  fma2(ACC[3][0],_pa,bA.x,ACC[3][0]); fma2(ACC[3][1],_pa,bA.y,ACC[3][1]); \
  fma2(ACC[3][2],_pa,bB.x,ACC[3][2]); fma2(ACC[3][3],_pa,bB.y,ACC[3][3]); \
}while(0)

// ---------------------------------------------------------------------------
// WKV-7 recurrence: one CTA per batch-head (bh = blockIdx.x, 0..31)
// Thread t: row i = t&63, half = t>>6 owns 32 state columns as 16 packed f32x2.
// 2 __syncthreads per step: dot/delta buffers double-buffered by step parity;
// y combined via per-half atomicAdd of r_i * partial (no reduce pass).
// ---------------------------------------------------------------------------
__device__ void wkv_block(float* smem, const float* R, const float* K, const float* V,
                          const float* W, const float* BN, float* out)
{
    const int bh   = blockIdx.x;
    const int b    = bh >> 4, h = bh & 15;
    const int tid  = threadIdx.x;
    const int i    = tid & 63;
    const int off  = (tid >> 6) * 32;
    const int base = bh * (2048 * 64);

    float* buf      = smem;           // 2 stages * 5 arrays * 1024 floats
    float* sh_dot   = smem + 10240;   // 2 * 128
    float* sh_delta = smem + 10496;   // 2 * 64

    u64 S2[16];
    #pragma unroll
    for (int q = 0; q < 16; ++q) S2[q] = 0ull;

    const float* g0 = R + base;
    const float* g1 = K + base;
    const float* g2 = V + base;
    const float* g3 = W + base;
    const float* g4 = BN + base;

    // prologue: issue blocks 0 and 1
    #pragma unroll
    for (int pb = 0; pb < 2; ++pb) {
        float* d = buf + pb * 5120;
        const float* srcs[5] = { g0 + pb*1024, g1 + pb*1024, g2 + pb*1024, g3 + pb*1024, g4 + pb*1024 };
        #pragma unroll
        for (int a = 0; a < 5; ++a) {
            float* da = d + a * 1024;
            const float* sa = srcs[a];
            for (int q = tid; q < 256; q += THREADS) cp_async16(da + q*4, sa + q*4);
        }
        cp_commit();
    }

    for (int blk = 0; blk < 128; ++blk) {
        cp_wait1();
        __syncthreads();
        const int stage = blk & 1;
        const float* bb = buf + stage * 5120;
        const float* Rb = bb;
        const float* Kb = bb + 1024;
        const float* Vb = bb + 2048;
        const float* Wb = bb + 3072;
        const float* Bb = bb + 4096;
        const int t0 = blk * 16;

        for (int s = 0; s < 16; ++s) {
            const int p = s & 1;
            const float* Kr = Kb + s * 64;

            // ---- phase 1: partial dot Sk over my 32 cols (packed) ----
            u64 k2[16];
            {
                const ulonglong2* kp = (const ulonglong2*)(Kr + off);
                #pragma unroll
                for (int q = 0; q < 8; ++q) { ulonglong2 t = kp[q]; k2[2*q] = t.x; k2[2*q+1] = t.y; }
            }
            u64 da[4] = {0ull, 0ull, 0ull, 0ull};
            #pragma unroll
            for (int q = 0; q < 16; ++q) fma2(da[q & 3], S2[q], k2[q], da[q & 3]);
            add2(da[0], da[0], da[1]); add2(da[2], da[2], da[3]); add2(da[0], da[0], da[2]);
            float2 pr = unpack2(da[0]);
            sh_dot[p*128 + tid] = pr.x + pr.y;
            __syncthreads();

            // ---- phase 2: delta (one thread per row) ----
            if (tid < 64)
                sh_delta[p*64 + i] = Vb[s*64 + i] - (sh_dot[p*128 + i] + sh_dot[p*128 + 64 + i]);
            __syncthreads();

            // ---- phase 3: state update + y, packed ----
            float wi  = Wb[s*64 + i];
            float bki = Bb[s*64 + i] * Kr[i];
            u64 w2 = pack2(wi, wi);
            u64 c2 = pack2(bki, bki);
            const ulonglong2* dp = (const ulonglong2*)(sh_delta + p*64 + off);
            u64 ya[4] = {0ull, 0ull, 0ull, 0ull};
            #pragma unroll
            for (int q = 0; q < 8; ++q) {
                ulonglong2 dq = dp[q];
                u64 t;
                mul2(t, c2, dq.x);
                fma2(S2[2*q],   S2[2*q],   w2, t);
                fma2(ya[(2*q) & 3],   S2[2*q],   k2[2*q],   ya[(2*q) & 3]);
                mul2(t, c2, dq.y);
                fma2(S2[2*q+1], S2[2*q+1], w2, t);
                fma2(ya[(2*q+1) & 3], S2[2*q+1], k2[2*q+1], ya[(2*q+1) & 3]);
            }
            add2(ya[0], ya[0], ya[1]); add2(ya[2], ya[2], ya[3]); add2(ya[0], ya[0], ya[2]);
            float2 yr = unpack2(ya[0]);
            float yp = yr.x + yr.y;
            // y_i = r_i*(half0+half1): each half adds its scaled partial directly
            atomicAdd(out + (size_t)(b*2048 + t0 + s)*1024 + h*64 + i, Rb[s*64 + i] * yp);
            // no barrier: next step writes parity p^1 buffers
        }

        // refill this stage for block blk+2
        const int nb = blk + 2;
        if (nb < 128) {
            float* d = buf + stage * 5120;
            const float* srcs[5] = { g0 + nb*1024, g1 + nb*1024, g2 + nb*1024, g3 + nb*1024, g4 + nb*1024 };
            #pragma unroll
            for (int a = 0; a < 5; ++a) {
                float* da = d + a * 1024;
                const float* sa = srcs[a];
                for (int q = tid; q < 256; q += THREADS) cp_async16(da + q*4, sa + q*4);
            }
        }
        cp_commit();
    }
}

// ---------------------------------------------------------------------------
// Mamba2 SSD chunked scan: one CTA per (b,h) (blockIdx.x - 32), sequential
// over 32 chunks of 64 tokens. All GEMM inner loops use packed fma.rn.f32x2.
// Running state held packed in registers (Sreg2), shared transposed copy St
// feeds the C*state GEMM.
// ---------------------------------------------------------------------------
__device__ void ssd_block(float* smem, const float* Xg, const float* Ag,
                          const float* Bg, const float* Cg, float* out)
{
    const int sb  = blockIdx.x - 32;
    const int b   = sb >> 4, h = sb & 15;
    const int tid = threadIdx.x;
    const int r0  = (tid & 15) * 4;   // a-dim tile base (l or p)
    const int c0  = (tid >> 4) * 8;   // b-dim tile base (s, p, or n)

    float* Ct   = smem;                  // [n][l], pre-scaled by exp(cum[l])
    float* Bt   = Ct  + 64 * SSTRIDE;    // [n][s], raw B
    float* Brw  = Bt  + 64 * SSTRIDE;    // [l][n], B * exp(Atot - cum[l])
    float* sX   = Brw + 64 * SSTRIDE;    // [l][p]
    float* Gt   = sX  + 64 * SSTRIDE;    // [s][l]
    float* St   = Gt  + 64 * SSTRIDE;    // [n][p], incoming state
    float* cum  = St  + 64 * SSTRIDE;    // [64]
    float* ecl  = cum + 64;              // exp(cum)
    float* recl = ecl + 64;              // exp(-cum)
    float* misc = recl + 64;             // [0] = exp(Atot)

    for (int idx = tid; idx < 64 * SSTRIDE; idx += THREADS) St[idx] = 0.f;

    u64 Sreg2[4][4];
    #pragma unroll
    for (int q = 0; q < 4; ++q)
        #pragma unroll
        for (int j = 0; j < 4; ++j) Sreg2[q][j] = 0ull;
    __syncthreads();

    for (int c = 0; c < 32; ++c) {
        const int tb = c * 64;

        // A row -> inclusive cumsum -> exp tables
        if (tid < 64) cum[tid] = Ag[(b*2048 + tb + tid)*16 + h];
        __syncthreads();
        if (tid == 0) {
            float s = 0.f;
            #pragma unroll
            for (int l = 0; l < 64; ++l) { s += cum[l]; cum[l] = s; }
        }
        __syncthreads();
        if (tid < 64) { float cl = cum[tid]; ecl[tid] = __expf(cl); recl[tid] = __expf(-cl); }
        if (tid == 0) misc[0] = __expf(cum[63]);
        __syncthreads();
        const float eA = misc[0];

        // load B, C, X tiles (with on-the-fly transposes + decay scaling)
        for (int idx = tid; idx < 4096; idx += THREADS) {
            int row = idx >> 6, col = idx & 63;
            int gix = ((b*2048 + tb + row)*16 + h)*64 + col;
            float bv = Bg[gix];
            Bt [col*SSTRIDE + row] = bv;
            Brw[row*SSTRIDE + col] = bv * (eA * recl[row]);
            Ct [col*SSTRIDE + row] = Cg[gix] * ecl[row];
            sX [row*SSTRIDE + col] = Xg[gix];
        }
        __syncthreads();

        // GEMM1: G[l,s] = sum_n Ctw[n][l] * B[n][s]   (Ctw includes exp(cum[l]))
        u64 acc2[4][4];
        #pragma unroll
        for (int q = 0; q < 4; ++q)
            #pragma unroll
            for (int j = 0; j < 4; ++j) acc2[q][j] = 0ull;
        #pragma unroll 4
        for (int n = 0; n < 64; ++n) {
            float4 a4 = *(const float4*)(Ct + n*SSTRIDE + r0);
            ulonglong2 bA = *(const ulonglong2*)(Bt + n*SSTRIDE + c0);
            ulonglong2 bB = *(const ulonglong2*)(Bt + n*SSTRIDE + c0 + 4);
            FMA32P(acc2, a4, bA, bB);
        }
        // unpack, mask s<=l, scale by exp(-cum[s]); store transposed Gt[s][l]
        {
            float accS[4][8];
            #pragma unroll
            for (int ii = 0; ii < 4; ++ii)
                #pragma unroll
                for (int jj = 0; jj < 4; ++jj) {
                    float2 v = unpack2(acc2[ii][jj]);
                    accS[ii][2*jj] = v.x; accS[ii][2*jj+1] = v.y;
                }
            #pragma unroll
            for (int ss = 0; ss < 8; ++ss) {
                int sidx = c0 + ss;
                float rs = recl[sidx];
                float4 v;
                v.x = (sidx <= r0 + 0) ? accS[0][ss] * rs : 0.f;
                v.y = (sidx <= r0 + 1) ? accS[1][ss] * rs : 0.f;
                v.z = (sidx <= r0 + 2) ? accS[2][ss] * rs : 0.f;
                v.w = (sidx <= r0 + 3) ? accS[3][ss] * rs : 0.f;
                *(float4*)(Gt + sidx*SSTRIDE + r0) = v;
            }
        }
        __syncthreads();

        // GEMM2+3 fused: Y[l,p] = sum_s G[l,s]X[s,p] + sum_n Ctw[n][l]St[n][p]
        #pragma unroll
        for (int q = 0; q < 4; ++q)
            #pragma unroll
            for (int j = 0; j < 4; ++j) acc2[q][j] = 0ull;
        #pragma unroll 4
        for (int s = 0; s < 64; ++s) {
            float4 a4 = *(const float4*)(Gt + s*SSTRIDE + r0);
            ulonglong2 bA = *(const ulonglong2*)(sX + s*SSTRIDE + c0);
            ulonglong2 bB = *(const ulonglong2*)(sX + s*SSTRIDE + c0 + 4);
            FMA32P(acc2, a4, bA, bB);
        }
        #pragma unroll 4
        for (int n = 0; n < 64; ++n) {
            float4 a4 = *(const float4*)(Ct + n*SSTRIDE + r0);
            ulonglong2 bA = *(const ulonglong2*)(St + n*SSTRIDE + c0);
            ulonglong2 bB = *(const ulonglong2*)(St + n*SSTRIDE + c0 + 4);
            FMA32P(acc2, a4, bA, bB);
        }
        #pragma unroll
        for (int ll = 0; ll < 4; ++ll) {
            int o = (b*2048 + tb + r0 + ll)*1024 + h*64 + c0;
            #pragma unroll
            for (int jj = 0; jj < 4; ++jj) {
                float2 v = unpack2(acc2[ll][jj]);
                atomicAdd(out + o + 2*jj,     v.x);
                atomicAdd(out + o + 2*jj + 1, v.y);
            }
        }

        // GEMM4 (state update): S[p,n] = eA*S + sum_l X[l,p] * Brw[l,n]
        {
            u64 eA2 = pack2(eA, eA);
            #pragma unroll
            for (int q = 0; q < 4; ++q)
                #pragma unroll
                for (int j = 0; j < 4; ++j) mul2(Sreg2[q][j], Sreg2[q][j], eA2);
        }
        #pragma unroll 4
        for (int l = 0; l < 64; ++l) {
            float4 a4 = *(const float4*)(sX + l*SSTRIDE + r0);
            ulonglong2 bA = *(const ulonglong2*)(Brw + l*SSTRIDE + c0);
            ulonglong2 bB = *(const ulonglong2*)(Brw + l*SSTRIDE + c0 + 4);
            FMA32P(Sreg2, a4, bA, bB);
        }
        __syncthreads();   // all GEMM3 reads of St done before overwrite
        {
            float Ss[4][8];
            #pragma unroll
            for (int ii = 0; ii < 4; ++ii)
                #pragma unroll
                for (int jj = 0; jj < 4; ++jj) {
                    float2 v = unpack2(Sreg2[ii][jj]);
                    Ss[ii][2*jj] = v.x; Ss[ii][2*jj+1] = v.y;
                }
            #pragma unroll
            for (int j = 0; j < 8; ++j) {
                float4 v = make_float4(Ss[0][j], Ss[1][j], Ss[2][j], Ss[3][j]);
                *(float4*)(St + (c0 + j)*SSTRIDE + r0) = v;
            }
        }
        __syncthreads();
    }
}

// ---------------------------------------------------------------------------
__global__ void __launch_bounds__(256)
zero_kernel(float4* out)
{
    out[blockIdx.x * 256 + threadIdx.x] = make_float4(0.f, 0.f, 0.f, 0.f);
}

__global__ void __launch_bounds__(THREADS, 1)
fused_kernel(const float* __restrict__ X, const float* __restrict__ A,
             const float* __restrict__ B, const float* __restrict__ C,
             const float* __restrict__ R, const float* __restrict__ K,
             const float* __restrict__ V, const float* __restrict__ W,
             const float* __restrict__ BN, float* __restrict__ out)
{
    extern __shared__ float smem[];
    if (blockIdx.x < 32) wkv_block(smem, R, K, V, W, BN, out);
    else                 ssd_block(smem, X, A, B, C, out);
}

extern "C" void kernel_launch(void* const* d_in, const int* in_sizes, int n_in,
                              void* d_out, int out_size)
{
    const float* X  = (const float*)d_in[0];
    const float* A  = (const float*)d_in[1];
    const float* B  = (const float*)d_in[2];
    const float* C  = (const float*)d_in[3];
    const float* R  = (const float*)d_in[4];
    const float* K  = (const float*)d_in[5];
    const float* V  = (const float*)d_in[6];
    const float* W  = (const float*)d_in[7];
    const float* BN = (const float*)d_in[8];
    float* out = (float*)d_out;

    // out_size = 2*2048*1024 = 4,194,304 floats = 1,048,576 float4
    zero_kernel<<<4096, 256>>>((float4*)out);

    cudaFuncSetAttribute(fused_kernel, cudaFuncAttributeMaxDynamicSharedMemorySize, SMEM_BYTES);
    fused_kernel<<<64, THREADS, SMEM_BYTES>>>(X, A, B, C, R, K, V, W, BN, out);
}